// round 12
// baseline (speedup 1.0000x reference)
#include <cuda_runtime.h>

// ---------------------------------------------------------------------------
// SSIM (16,3,512,512) fp32, 11x11 gaussian (sigma=1.5), zero padding.
// Round-12 (best: R9 82.4us; R10 cp8-loader and R11 parity-banks both lost):
//  * 32B-group layout marries R9's loader to R10's consumer:
//      load: group g = [img1 chunk (a0..a3) | img2 chunk (b0..b3)], two cp16
//      per group -> same 792 copies/block as R9.
//      pre-pass: thread owns whole 32B groups (read set == write set ->
//      in-place, race-free), rewrites as (c0,d0,c1,d1,c2,d2,c3,d3).
//      consumer: slot[col]=u64(c,d) at byte col*8 -> 11 conflict-free
//      LDS.64 + 33 fma2 per row (no packs, no parity offsets).
// ---------------------------------------------------------------------------

#define IMG_H 512
#define IMG_W 512
#define N_PLANES 48
#define N_BLOCKS (48 * 4 * 16)
#define TOTAL_PIX 12582912.0

#define GW0 0.26601172f
#define GW1 0.21300554f
#define GW2 0.10936069f
#define GW3 0.03600077f
#define GW4 0.00759876f
#define GW5 0.00102842f

__device__ double g_acc;
__device__ unsigned int g_count;

typedef unsigned long long u64;

__device__ __forceinline__ u64 pk2(float lo, float hi) {
    u64 r; asm("mov.b64 %0, {%1, %2};" : "=l"(r) : "f"(lo), "f"(hi)); return r;
}
__device__ __forceinline__ float2 upk2(u64 v) {
    float2 r; asm("mov.b64 {%0, %1}, %2;" : "=f"(r.x), "=f"(r.y) : "l"(v)); return r;
}
__device__ __forceinline__ u64 fma2(u64 a, u64 b, u64 c) {
    u64 d; asm("fma.rn.f32x2 %0, %1, %2, %3;" : "=l"(d) : "l"(a), "l"(b), "l"(c)); return d;
}
__device__ __forceinline__ u64 mul2(u64 a, u64 b) {
    u64 d; asm("mul.rn.f32x2 %0, %1, %2;" : "=l"(d) : "l"(a), "l"(b)); return d;
}
__device__ __forceinline__ void cp16(unsigned dst, const float* src, unsigned rs) {
    asm volatile("cp.async.cg.shared.global [%0], [%1], 16, %2;"
                 :: "r"(dst), "l"(src), "r"(rs));
}

// local cols 0..143  <->  global cols col0-8 .. col0+135
// row = 36 groups x 32B; after pre-pass slot[col] = u64(c,d) at byte col*8.
// thread tx's taps: slots tx+3 .. tx+13 (max 140 < 144)
#define NGRP  36                   // 32B groups per row
#define ROW_B (NGRP * 32)          // 1152 bytes
#define BUF_B (11 * ROW_B)         // 12672 bytes
#define PRE_TASKS (11 * NGRP)      // 396

__global__ __launch_bounds__(128, 7)
void ssim_kernel(const float* __restrict__ img1, const float* __restrict__ img2,
                 float* __restrict__ out) {
    const int plane = blockIdx.x;     // 0..47
    const int strip = blockIdx.y;     // 0..3
    const int band  = blockIdx.z;     // 0..15  (row bands of 32)
    const int tx    = threadIdx.x;

    const int col0 = strip * 128;
    const int row0 = band * 32;

    const float* __restrict__ p1 = img1 + (size_t)plane * (IMG_H * IMG_W);
    const float* __restrict__ p2 = img2 + (size_t)plane * (IMG_H * IMG_W);

    // [buf][row][144 u64 slots]
    __shared__ __align__(16) u64 smem[2][11][2 * NGRP * 2];

    unsigned sbase;
    asm("{ .reg .u64 t; cvta.to.shared.u64 t, %1; cvt.u32.u64 %0, t; }"
        : "=r"(sbase) : "l"((const void*)smem));

    // ---- loader: thread tx<72 owns one 16B chunk: group g=tx>>1, img=tx&1
    const int  lgrp  = tx >> 1;
    const int  limg  = tx & 1;
    const int  lgcol = col0 - 8 + lgrp * 4;
    const bool lcolok = (tx < 2 * NGRP) && ((unsigned)lgcol < (unsigned)IMG_W);
    const float* __restrict__ lbase = limg ? p2 : p1;
    const unsigned ldst = sbase + (unsigned)(lgrp * 32 + limg * 16);

    const u64 W2_0 = pk2(GW0, GW0), W2_1 = pk2(GW1, GW1), W2_2 = pk2(GW2, GW2);
    const u64 W2_3 = pk2(GW3, GW3), W2_4 = pk2(GW4, GW4), W2_5 = pk2(GW5, GW5);
    const u64 WT[11] = {W2_5, W2_4, W2_3, W2_2, W2_1, W2_0,
                        W2_1, W2_2, W2_3, W2_4, W2_5};
    const u64 NEG1 = pk2(-1.f, -1.f);

    u64 ring01[11], ringq[11];
#pragma unroll
    for (int k = 0; k < 11; ++k) { ring01[k] = 0ull; ringq[k] = 0ull; }

    float acc = 0.f;
    const float C1  = 1e-4f;
    const float C2  = 9e-4f;
    const float C2E = 9e-4f + 1e-6f;

    auto load_chunk = [&](int t, int bb) {
        if (tx < 2 * NGRP) {
            const int base = row0 - 5 + t * 11;
            const unsigned dbase = ldst + (unsigned)(bb * BUF_B);
#pragma unroll
            for (int r = 0; r < 11; ++r) {
                const int y = base + r;
                const bool ok = lcolok && ((unsigned)y < (unsigned)IMG_H);
                const int goff = ok ? (y * IMG_W + lgcol) : 0;
                cp16(dbase + (unsigned)(r * ROW_B), lbase + goff, ok ? 16u : 0u);
            }
        }
        asm volatile("cp.async.commit_group;");
    };

    load_chunk(0, 0);

    // input rows n = t*11 + k, 4 chunks; outputs for n in [10, 42)
    for (int t = 0; t < 4; ++t) {
        const int cur = t & 1;
        if (t < 3) {
            load_chunk(t + 1, cur ^ 1);
            asm volatile("cp.async.wait_group 1;");
        } else {
            asm volatile("cp.async.wait_group 0;");
        }
        __syncthreads();   // chunk t raw data visible

        // pre-pass: 32B group (a0..a3, b0..b3) -> (c0,d0,c1,d1, c2,d2,c3,d3)
        // in place; thread owns whole groups -> race-free.
        {
            float4* G = (float4*)smem[cur];   // 2 float4 per group
#pragma unroll 1
            for (int j = tx; j < PRE_TASKS; j += 128) {
                float4* pa = G + 2 * j;
                const float4 A = pa[0];       // a0 a1 a2 a3
                const float4 B = pa[1];       // b0 b1 b2 b3
                float4 o0, o1;
                o0.x = A.x + B.x;  o0.y = A.x - B.x;   // c0 d0
                o0.z = A.y + B.y;  o0.w = A.y - B.y;   // c1 d1
                o1.x = A.z + B.z;  o1.y = A.z - B.z;   // c2 d2
                o1.z = A.w + B.w;  o1.w = A.w - B.w;   // c3 d3
                pa[0] = o0;
                pa[1] = o1;
            }
        }
        __syncthreads();   // (c,d) slots visible to all

#pragma unroll
        for (int k = 0; k < 11; ++k) {
            const u64* srow = smem[cur][k];
            u64 h01 = 0ull, hq = 0ull;
#pragma unroll
            for (int i = 0; i < 11; ++i) {
                const u64 vv = srow[tx + 3 + i];   // LDS.64: (c,d), conflict-free
                const u64 w  = WT[i];
                h01 = fma2(w, vv, h01);            // (+wc, +wd)
                const u64 p = mul2(w, vv);         // (wc, wd)
                hq  = fma2(p, vv, hq);             // (+wc^2, +wd^2)
            }
            ring01[k] = h01;
            ringq [k] = hq;

            const int n = t * 11 + k;
            if (n >= 10 && n < 42) {
                u64 m12 = 0ull, qv = 0ull;
#pragma unroll
                for (int j = 0; j < 11; ++j) {
                    const int s = (k + 1 + j) % 11;   // static after unroll
                    const u64 w = WT[j];
                    m12 = fma2(w, ring01[s], m12);    // (C, D)
                    qv  = fma2(w, ringq [s], qv);     // (Qc, Qd)
                }
                const u64 cd2 = mul2(m12, m12);           // (C^2, D^2)
                const u64 ev  = fma2(cd2, NEG1, qv);      // (Ec, Ed)
                const float2 s2 = upk2(cd2);
                const float2 e2 = upk2(ev);
                const float M = s2.x - s2.y;   // 4*mu1*mu2
                const float P = s2.x + s2.y;   // 2*(mu1^2+mu2^2)
                const float S = e2.x - e2.y;   // 4*sig12
                const float T = e2.x + e2.y;   // 2*sigpp
                const float num = fmaf(0.5f, M, C1) * fmaf(0.5f, S, C2);
                const float den = fmaf(0.5f, P, C1) * fmaf(0.5f, T, C2E);
                acc += __fdividef(num, den);
            }
        }
        __syncthreads();   // buffer cur free for chunk t+2's cp.async
    }

#pragma unroll
    for (int o = 16; o > 0; o >>= 1)
        acc += __shfl_xor_sync(0xFFFFFFFFu, acc, o);

    __shared__ float wsum[4];
    if ((tx & 31) == 0) wsum[tx >> 5] = acc;
    __syncthreads();

    if (tx == 0) {
        const float s = wsum[0] + wsum[1] + wsum[2] + wsum[3];
        atomicAdd(&g_acc, (double)s);
        __threadfence();
        const unsigned int done = atomicAdd(&g_count, 1u);
        if (done == (unsigned)(N_BLOCKS - 1)) {
            const double total = atomicAdd(&g_acc, 0.0);
            out[0] = (float)(total / TOTAL_PIX);
            g_acc = 0.0;
            g_count = 0u;
            __threadfence();
        }
    }
}

extern "C" void kernel_launch(void* const* d_in, const int* in_sizes, int n_in,
                              void* d_out, int out_size) {
    const float* img1 = (const float*)d_in[0];
    const float* img2 = (const float*)d_in[1];
    float* out = (float*)d_out;
    (void)in_sizes; (void)n_in; (void)out_size;

    dim3 grid(N_PLANES, 4, 16);
    ssim_kernel<<<grid, 128>>>(img1, img2, out);
}

// round 13
// speedup vs baseline: 1.1816x; 1.1816x over previous
#include <cuda_runtime.h>

// ---------------------------------------------------------------------------
// SSIM (16,3,512,512) fp32, 11x11 gaussian (sigma=1.5), zero padding.
// Round-13 = R9 (82.4us, best) + two targeted changes:
//  * 65-output bands (T=7 chunks of 11 rows, grid 48x4x8=1536): halo row
//    overhead 42/32=1.31x -> 77/65=1.18x on horizontal+load+prepass work.
//    Last band emits 57 outputs (guarded).
//  * float4 pre-pass on the planar layout (2xLDS.128 + 4 packed ops +
//    2xSTS.128 per 2 slots) -- halves pre-pass instruction count.
// Loader, consumer, ring, epilogue identical to R9.
// ---------------------------------------------------------------------------

#define IMG_H 512
#define IMG_W 512
#define N_PLANES 48
#define N_BANDS 8
#define BAND_OUT 65                 // outputs per full band (last band: 57)
#define N_BLOCKS (48 * 4 * N_BANDS)
#define TOTAL_PIX 12582912.0
#define T_CHUNKS 7

#define GW0 0.26601172f
#define GW1 0.21300554f
#define GW2 0.10936069f
#define GW3 0.03600077f
#define GW4 0.00759876f
#define GW5 0.00102842f

__device__ double g_acc;
__device__ unsigned int g_count;

typedef unsigned long long u64;

__device__ __forceinline__ u64 pk2(float lo, float hi) {
    u64 r; asm("mov.b64 %0, {%1, %2};" : "=l"(r) : "f"(lo), "f"(hi)); return r;
}
__device__ __forceinline__ float2 upk2(u64 v) {
    float2 r; asm("mov.b64 {%0, %1}, %2;" : "=f"(r.x), "=f"(r.y) : "l"(v)); return r;
}
__device__ __forceinline__ u64 fma2(u64 a, u64 b, u64 c) {
    u64 d; asm("fma.rn.f32x2 %0, %1, %2, %3;" : "=l"(d) : "l"(a), "l"(b), "l"(c)); return d;
}
__device__ __forceinline__ u64 mul2(u64 a, u64 b) {
    u64 d; asm("mul.rn.f32x2 %0, %1, %2;" : "=l"(d) : "l"(a), "l"(b)); return d;
}
__device__ __forceinline__ void cp16(unsigned dst, const float* src, unsigned rs) {
    asm volatile("cp.async.cg.shared.global [%0], [%1], 16, %2;"
                 :: "r"(dst), "l"(src), "r"(rs));
}

// smem row: 144 floats per plane, global cols [col0-8, col0+136)
// thread tx's 11-tap window: smem idx tx+3 .. tx+13 (max 140 < 144)
#define RW 144
#define NCP 36                           // 16B chunks per row per plane
#define ROW_STRIDE_B (2 * RW * 4)        // 1152 bytes (plane a + plane b)
#define BUF_STRIDE_B (11 * 2 * RW * 4)   // 12672 bytes
#define PRE_TASKS (11 * NCP)             // 396 float4-pair tasks

__global__ __launch_bounds__(128, 7)
void ssim_kernel(const float* __restrict__ img1, const float* __restrict__ img2,
                 float* __restrict__ out) {
    const int plane = blockIdx.x;     // 0..47
    const int strip = blockIdx.y;     // 0..3
    const int band  = blockIdx.z;     // 0..7
    const int tx    = threadIdx.x;

    const int col0 = strip * 128;
    const int row0 = band * BAND_OUT;
    const int nlim = 10 + ((row0 + BAND_OUT <= IMG_H) ? BAND_OUT : (IMG_H - row0));

    const float* __restrict__ p1 = img1 + (size_t)plane * (IMG_H * IMG_W);
    const float* __restrict__ p2 = img2 + (size_t)plane * (IMG_H * IMG_W);

    // [buf][row][plane(a->c / b->d)][col]
    __shared__ __align__(16) float smem[2][11][2][RW];

    unsigned sbase;
    asm("{ .reg .u64 t; cvta.to.shared.u64 t, %1; cvt.u32.u64 %0, t; }"
        : "=r"(sbase) : "l"((const void*)smem));

    // loader: thread tx<72 owns one 16B chunk column (plane, pos)
    const int  larr  = (tx >= NCP) ? 1 : 0;
    const int  lpos  = tx - NCP * larr;
    const int  lgcol = col0 - 8 + lpos * 4;
    const bool lcolok = (tx < 2 * NCP) && ((unsigned)lgcol < (unsigned)IMG_W);
    const float* __restrict__ lbase = larr ? p2 : p1;
    const unsigned ldst = sbase + (unsigned)((larr * RW + lpos * 4) * 4);

    const u64 W2_0 = pk2(GW0, GW0), W2_1 = pk2(GW1, GW1), W2_2 = pk2(GW2, GW2);
    const u64 W2_3 = pk2(GW3, GW3), W2_4 = pk2(GW4, GW4), W2_5 = pk2(GW5, GW5);
    const u64 WT[11] = {W2_5, W2_4, W2_3, W2_2, W2_1, W2_0,
                        W2_1, W2_2, W2_3, W2_4, W2_5};
    const u64 NEG1 = pk2(-1.f, -1.f);

    u64 ring01[11], ringq[11];
#pragma unroll
    for (int k = 0; k < 11; ++k) { ring01[k] = 0ull; ringq[k] = 0ull; }

    float acc = 0.f;
    const float C1  = 1e-4f;
    const float C2  = 9e-4f;
    const float C2E = 9e-4f + 1e-6f;

    auto load_chunk = [&](int t, int bb) {
        if (tx < 2 * NCP) {
            const int base = row0 - 5 + t * 11;
            const unsigned dbase = ldst + (unsigned)(bb * BUF_STRIDE_B);
#pragma unroll
            for (int r = 0; r < 11; ++r) {
                const int y = base + r;
                const bool ok = lcolok && ((unsigned)y < (unsigned)IMG_H);
                const int goff = ok ? (y * IMG_W + lgcol) : 0;
                cp16(dbase + (unsigned)(r * ROW_STRIDE_B), lbase + goff,
                     ok ? 16u : 0u);
            }
        }
        asm volatile("cp.async.commit_group;");
    };

    load_chunk(0, 0);

    // input rows n = t*11 + k; outputs for n in [10, nlim)
    for (int t = 0; t < T_CHUNKS; ++t) {
        const int cur = t & 1;
        if (t < T_CHUNKS - 1) {
            load_chunk(t + 1, cur ^ 1);
            asm volatile("cp.async.wait_group 1;");
        } else {
            asm volatile("cp.async.wait_group 0;");
        }
        __syncthreads();   // chunk t raw data visible

        // pre-pass (float4): quad g of row r: A=(a0..a3), B=(b0..b3) ->
        // A'=(c0..c3), B'=(d0..d3). read set == write set -> race-free.
        {
            char* base = (char*)smem[cur];
#pragma unroll 1
            for (int j = tx; j < PRE_TASKS; j += 128) {
                const int r = j / NCP;
                const int g = j - r * NCP;
                float4* pa = (float4*)(base + r * ROW_STRIDE_B + g * 16);
                float4* pb = (float4*)((char*)pa + RW * 4);
                const float4 A = *pa;
                const float4 B = *pb;
                float4 cq, dq;
                cq.x = A.x + B.x;  dq.x = A.x - B.x;
                cq.y = A.y + B.y;  dq.y = A.y - B.y;
                cq.z = A.z + B.z;  dq.z = A.z - B.z;
                cq.w = A.w + B.w;  dq.w = A.w - B.w;
                *pa = cq;
                *pb = dq;
            }
        }
        __syncthreads();   // (c,d) visible to all

#pragma unroll
        for (int k = 0; k < 11; ++k) {
            const float* sc = smem[cur][k][0];
            const float* sd = smem[cur][k][1];
            u64 h01 = 0ull, hq = 0ull;
#pragma unroll
            for (int i = 0; i < 11; ++i) {
                const u64 vv = pk2(sc[tx + 3 + i], sd[tx + 3 + i]);  // (c,d)
                const u64 w  = WT[i];
                h01 = fma2(w, vv, h01);            // (+wc, +wd)
                const u64 p = mul2(w, vv);         // (wc, wd)
                hq  = fma2(p, vv, hq);             // (+wc^2, +wd^2)
            }
            ring01[k] = h01;
            ringq [k] = hq;

            const int n = t * 11 + k;
            if (n >= 10 && n < nlim) {
                u64 m12 = 0ull, qv = 0ull;
#pragma unroll
                for (int j = 0; j < 11; ++j) {
                    const int s = (k + 1 + j) % 11;   // static after unroll
                    const u64 w = WT[j];
                    m12 = fma2(w, ring01[s], m12);    // (C, D)
                    qv  = fma2(w, ringq [s], qv);     // (Qc, Qd)
                }
                const u64 cd2 = mul2(m12, m12);           // (C^2, D^2)
                const u64 ev  = fma2(cd2, NEG1, qv);      // (Ec, Ed)
                const float2 s2 = upk2(cd2);
                const float2 e2 = upk2(ev);
                const float M = s2.x - s2.y;   // 4*mu1*mu2
                const float P = s2.x + s2.y;   // 2*(mu1^2+mu2^2)
                const float S = e2.x - e2.y;   // 4*sig12
                const float T = e2.x + e2.y;   // 2*sigpp
                const float num = fmaf(0.5f, M, C1) * fmaf(0.5f, S, C2);
                const float den = fmaf(0.5f, P, C1) * fmaf(0.5f, T, C2E);
                acc += __fdividef(num, den);
            }
        }
        __syncthreads();   // buffer cur free for chunk t+2's cp.async
    }

#pragma unroll
    for (int o = 16; o > 0; o >>= 1)
        acc += __shfl_xor_sync(0xFFFFFFFFu, acc, o);

    __shared__ float wsum[4];
    if ((tx & 31) == 0) wsum[tx >> 5] = acc;
    __syncthreads();

    if (tx == 0) {
        const float s = wsum[0] + wsum[1] + wsum[2] + wsum[3];
        atomicAdd(&g_acc, (double)s);
        __threadfence();
        const unsigned int done = atomicAdd(&g_count, 1u);
        if (done == (unsigned)(N_BLOCKS - 1)) {
            const double total = atomicAdd(&g_acc, 0.0);
            out[0] = (float)(total / TOTAL_PIX);
            g_acc = 0.0;
            g_count = 0u;
            __threadfence();
        }
    }
}

extern "C" void kernel_launch(void* const* d_in, const int* in_sizes, int n_in,
                              void* d_out, int out_size) {
    const float* img1 = (const float*)d_in[0];
    const float* img2 = (const float*)d_in[1];
    float* out = (float*)d_out;
    (void)in_sizes; (void)n_in; (void)out_size;

    dim3 grid(N_PLANES, 4, N_BANDS);
    ssim_kernel<<<grid, 128>>>(img1, img2, out);
}

// round 14
// speedup vs baseline: 1.2409x; 1.0502x over previous
#include <cuda_runtime.h>

// ---------------------------------------------------------------------------
// SSIM (16,3,512,512) fp32, 11x11 gaussian (sigma=1.5), zero padding.
// Round-14 (base R13, 80.4us):
//  * out-of-place transform: coalesced planar cp16 loader -> raw staging
//    region; pre-pass writes column-interleaved u64(c,d) slots into a
//    SEPARATE ileav region (disjoint src/dst -> race-free, no layout
//    compromise). cp(t+1) issues after the transform and overlaps consume.
//  * consumer: 11 conflict-free LDS.64 + 33 fma2 per row, zero packs
//    (saves 11 LDS.32 + 11 movs per row vs R13).
//  * smem unchanged (raw 12.7KB + ileav 12.7KB = 25.4KB, 7 blocks/SM);
//    loader, ring, vertical, epilogue identical to R13.
// ---------------------------------------------------------------------------

#define IMG_H 512
#define IMG_W 512
#define N_PLANES 48
#define N_BANDS 8
#define BAND_OUT 65                 // outputs per full band (last band: 57)
#define N_BLOCKS (48 * 4 * N_BANDS)
#define TOTAL_PIX 12582912.0
#define T_CHUNKS 7

#define GW0 0.26601172f
#define GW1 0.21300554f
#define GW2 0.10936069f
#define GW3 0.03600077f
#define GW4 0.00759876f
#define GW5 0.00102842f

__device__ double g_acc;
__device__ unsigned int g_count;

typedef unsigned long long u64;

__device__ __forceinline__ u64 pk2(float lo, float hi) {
    u64 r; asm("mov.b64 %0, {%1, %2};" : "=l"(r) : "f"(lo), "f"(hi)); return r;
}
__device__ __forceinline__ float2 upk2(u64 v) {
    float2 r; asm("mov.b64 {%0, %1}, %2;" : "=f"(r.x), "=f"(r.y) : "l"(v)); return r;
}
__device__ __forceinline__ u64 fma2(u64 a, u64 b, u64 c) {
    u64 d; asm("fma.rn.f32x2 %0, %1, %2, %3;" : "=l"(d) : "l"(a), "l"(b), "l"(c)); return d;
}
__device__ __forceinline__ u64 mul2(u64 a, u64 b) {
    u64 d; asm("mul.rn.f32x2 %0, %1, %2;" : "=l"(d) : "l"(a), "l"(b)); return d;
}
__device__ __forceinline__ void cp16(unsigned dst, const float* src, unsigned rs) {
    asm volatile("cp.async.cg.shared.global [%0], [%1], 16, %2;"
                 :: "r"(dst), "l"(src), "r"(rs));
}

// local cols 0..143  <->  global cols col0-8 .. col0+135
// consumer taps for thread tx: slots tx+3 .. tx+13 (max 140 < 144)
#define RW 144
#define NCP 36                            // 16B chunks per row per plane
#define RAW_ROW_B   (2 * RW * 4)          // 1152 B: plane a | plane b
#define RAW_BYTES   (11 * RAW_ROW_B)      // 12672
#define IL_ROW_U64  RW                    // 144 u64 slots per row
#define PRE_TASKS   (11 * NCP)            // 396

__global__ __launch_bounds__(128, 7)
void ssim_kernel(const float* __restrict__ img1, const float* __restrict__ img2,
                 float* __restrict__ out) {
    const int plane = blockIdx.x;     // 0..47
    const int strip = blockIdx.y;     // 0..3
    const int band  = blockIdx.z;     // 0..7
    const int tx    = threadIdx.x;

    const int col0 = strip * 128;
    const int row0 = band * BAND_OUT;
    const int nlim = 10 + ((row0 + BAND_OUT <= IMG_H) ? BAND_OUT : (IMG_H - row0));

    const float* __restrict__ p1 = img1 + (size_t)plane * (IMG_H * IMG_W);
    const float* __restrict__ p2 = img2 + (size_t)plane * (IMG_H * IMG_W);

    __shared__ __align__(16) float raw[11][2][RW];          // planar staging
    __shared__ __align__(16) u64   ileav[11][IL_ROW_U64];   // (c,d) per col

    unsigned rbase;
    asm("{ .reg .u64 t; cvta.to.shared.u64 t, %1; cvt.u32.u64 %0, t; }"
        : "=r"(rbase) : "l"((const void*)raw));

    // loader: thread tx<72 owns one 16B chunk column (plane, pos) -- coalesced
    const int  larr  = (tx >= NCP) ? 1 : 0;
    const int  lpos  = tx - NCP * larr;
    const int  lgcol = col0 - 8 + lpos * 4;
    const bool lcolok = (tx < 2 * NCP) && ((unsigned)lgcol < (unsigned)IMG_W);
    const float* __restrict__ lbase = larr ? p2 : p1;
    const unsigned ldst = rbase + (unsigned)((larr * RW + lpos * 4) * 4);

    const u64 W2_0 = pk2(GW0, GW0), W2_1 = pk2(GW1, GW1), W2_2 = pk2(GW2, GW2);
    const u64 W2_3 = pk2(GW3, GW3), W2_4 = pk2(GW4, GW4), W2_5 = pk2(GW5, GW5);
    const u64 WT[11] = {W2_5, W2_4, W2_3, W2_2, W2_1, W2_0,
                        W2_1, W2_2, W2_3, W2_4, W2_5};
    const u64 NEG1 = pk2(-1.f, -1.f);

    u64 ring01[11], ringq[11];
#pragma unroll
    for (int k = 0; k < 11; ++k) { ring01[k] = 0ull; ringq[k] = 0ull; }

    float acc = 0.f;
    const float C1  = 1e-4f;
    const float C2  = 9e-4f;
    const float C2E = 9e-4f + 1e-6f;

    auto load_chunk = [&](int t) {
        if (tx < 2 * NCP) {
            const int base = row0 - 5 + t * 11;
#pragma unroll
            for (int r = 0; r < 11; ++r) {
                const int y = base + r;
                const bool ok = lcolok && ((unsigned)y < (unsigned)IMG_H);
                const int goff = ok ? (y * IMG_W + lgcol) : 0;
                cp16(ldst + (unsigned)(r * RAW_ROW_B), lbase + goff,
                     ok ? 16u : 0u);
            }
        }
        asm volatile("cp.async.commit_group;");
    };

    load_chunk(0);

    // input rows n = t*11 + k; outputs for n in [10, nlim)
    for (int t = 0; t < T_CHUNKS; ++t) {
        asm volatile("cp.async.wait_group 0;");
        __syncthreads();   // raw = chunk t; also: ileav fully consumed (t-1)

        // transform raw -> ileav (out of place, disjoint): quad g of row r
        {
#pragma unroll 1
            for (int j = tx; j < PRE_TASKS; j += 128) {
                const int r = j / NCP;
                const int g = j - r * NCP;
                const float4 A = *(const float4*)&raw[r][0][g * 4];  // a0..a3
                const float4 B = *(const float4*)&raw[r][1][g * 4];  // b0..b3
                float4 o0, o1;
                o0.x = A.x + B.x;  o0.y = A.x - B.x;   // c0 d0
                o0.z = A.y + B.y;  o0.w = A.y - B.y;   // c1 d1
                o1.x = A.z + B.z;  o1.y = A.z - B.z;   // c2 d2
                o1.z = A.w + B.w;  o1.w = A.w - B.w;   // c3 d3
                float4* dst = (float4*)&ileav[r][g * 4];
                dst[0] = o0;
                dst[1] = o1;
            }
        }
        __syncthreads();   // ileav ready; raw free

        if (t < T_CHUNKS - 1) load_chunk(t + 1);   // overlaps consume below

#pragma unroll
        for (int k = 0; k < 11; ++k) {
            const u64* srow = ileav[k];
            u64 h01 = 0ull, hq = 0ull;
#pragma unroll
            for (int i = 0; i < 11; ++i) {
                const u64 vv = srow[tx + 3 + i];   // LDS.64 (c,d)
                const u64 w  = WT[i];
                h01 = fma2(w, vv, h01);            // (+wc, +wd)
                const u64 p = mul2(w, vv);         // (wc, wd)
                hq  = fma2(p, vv, hq);             // (+wc^2, +wd^2)
            }
            ring01[k] = h01;
            ringq [k] = hq;

            const int n = t * 11 + k;
            if (n >= 10 && n < nlim) {
                u64 m12 = 0ull, qv = 0ull;
#pragma unroll
                for (int j = 0; j < 11; ++j) {
                    const int s = (k + 1 + j) % 11;   // static after unroll
                    const u64 w = WT[j];
                    m12 = fma2(w, ring01[s], m12);    // (C, D)
                    qv  = fma2(w, ringq [s], qv);     // (Qc, Qd)
                }
                const u64 cd2 = mul2(m12, m12);           // (C^2, D^2)
                const u64 ev  = fma2(cd2, NEG1, qv);      // (Ec, Ed)
                const float2 s2 = upk2(cd2);
                const float2 e2 = upk2(ev);
                const float M = s2.x - s2.y;   // 4*mu1*mu2
                const float P = s2.x + s2.y;   // 2*(mu1^2+mu2^2)
                const float S = e2.x - e2.y;   // 4*sig12
                const float T = e2.x + e2.y;   // 2*sigpp
                const float num = fmaf(0.5f, M, C1) * fmaf(0.5f, S, C2);
                const float den = fmaf(0.5f, P, C1) * fmaf(0.5f, T, C2E);
                acc += __fdividef(num, den);
            }
        }
        // no trailing sync needed: next iteration's top sync (after
        // wait_group) is the "ileav consumed" barrier.
    }

#pragma unroll
    for (int o = 16; o > 0; o >>= 1)
        acc += __shfl_xor_sync(0xFFFFFFFFu, acc, o);

    __shared__ float wsum[4];
    if ((tx & 31) == 0) wsum[tx >> 5] = acc;
    __syncthreads();

    if (tx == 0) {
        const float s = wsum[0] + wsum[1] + wsum[2] + wsum[3];
        atomicAdd(&g_acc, (double)s);
        __threadfence();
        const unsigned int done = atomicAdd(&g_count, 1u);
        if (done == (unsigned)(N_BLOCKS - 1)) {
            const double total = atomicAdd(&g_acc, 0.0);
            out[0] = (float)(total / TOTAL_PIX);
            g_acc = 0.0;
            g_count = 0u;
            __threadfence();
        }
    }
}

extern "C" void kernel_launch(void* const* d_in, const int* in_sizes, int n_in,
                              void* d_out, int out_size) {
    const float* img1 = (const float*)d_in[0];
    const float* img2 = (const float*)d_in[1];
    float* out = (float*)d_out;
    (void)in_sizes; (void)n_in; (void)out_size;

    dim3 grid(N_PLANES, 4, N_BANDS);
    ssim_kernel<<<grid, 128>>>(img1, img2, out);
}

// round 15
// speedup vs baseline: 1.2445x; 1.0029x over previous
#include <cuda_runtime.h>

// ---------------------------------------------------------------------------
// SSIM (16,3,512,512) fp32, 11x11 gaussian (sigma=1.5), zero padding.
// Round-15 (base R14, 76.5us):
//  * LPT band schedule: the 19us gap to the ~55-60us pipe floor is wave
//    quantization (1536 blocks / 1036 resident = 1.48 waves, 78% fill,
//    occ 34.2/43.75). Variable band sizes -- 6x65 rows launched first,
//    then 2x35 + 2x26 as drain fillers (z is slowest-varying in bid, so
//    small bands execute last). Avg halo 1.195 (~R14's 1.18) but the
//    final drain is made of short blocks -> fill ~90%.
//  * grid 48 x 4 x 10 = 1920 blocks; chunk count per band = (size+20)/11.
//  * loader / out-of-place transform / consumer / ring / epilogue: R14.
// ---------------------------------------------------------------------------

#define IMG_H 512
#define IMG_W 512
#define N_PLANES 48
#define N_BANDS 10
#define N_BLOCKS (48 * 4 * N_BANDS)
#define TOTAL_PIX 12582912.0

#define GW0 0.26601172f
#define GW1 0.21300554f
#define GW2 0.10936069f
#define GW3 0.03600077f
#define GW4 0.00759876f
#define GW5 0.00102842f

__device__ double g_acc;
__device__ unsigned int g_count;

typedef unsigned long long u64;

__device__ __forceinline__ u64 pk2(float lo, float hi) {
    u64 r; asm("mov.b64 %0, {%1, %2};" : "=l"(r) : "f"(lo), "f"(hi)); return r;
}
__device__ __forceinline__ float2 upk2(u64 v) {
    float2 r; asm("mov.b64 {%0, %1}, %2;" : "=f"(r.x), "=f"(r.y) : "l"(v)); return r;
}
__device__ __forceinline__ u64 fma2(u64 a, u64 b, u64 c) {
    u64 d; asm("fma.rn.f32x2 %0, %1, %2, %3;" : "=l"(d) : "l"(a), "l"(b), "l"(c)); return d;
}
__device__ __forceinline__ u64 mul2(u64 a, u64 b) {
    u64 d; asm("mul.rn.f32x2 %0, %1, %2;" : "=l"(d) : "l"(a), "l"(b)); return d;
}
__device__ __forceinline__ void cp16(unsigned dst, const float* src, unsigned rs) {
    asm volatile("cp.async.cg.shared.global [%0], [%1], 16, %2;"
                 :: "r"(dst), "l"(src), "r"(rs));
}

// local cols 0..143  <->  global cols col0-8 .. col0+135
// consumer taps for thread tx: slots tx+3 .. tx+13 (max 140 < 144)
#define RW 144
#define NCP 36                            // 16B chunks per row per plane
#define RAW_ROW_B   (2 * RW * 4)          // 1152 B: plane a | plane b
#define PRE_TASKS   (11 * NCP)            // 396

__global__ __launch_bounds__(128, 7)
void ssim_kernel(const float* __restrict__ img1, const float* __restrict__ img2,
                 float* __restrict__ out) {
    // LPT band table: big bands first (low z), small drain-fillers last.
    const int BSTART[N_BANDS] = {0, 65, 130, 195, 260, 325, 390, 425, 460, 486};
    const int BSIZE [N_BANDS] = {65, 65, 65, 65, 65, 65, 35, 35, 26, 26};

    const int plane = blockIdx.x;     // 0..47
    const int strip = blockIdx.y;     // 0..3
    const int band  = blockIdx.z;     // 0..9
    const int tx    = threadIdx.x;

    const int col0 = strip * 128;
    const int row0 = BSTART[band];
    const int bsz  = BSIZE[band];
    const int nlim = 10 + bsz;
    const int tmax = (bsz + 20) / 11;     // ceil((bsz+10)/11)

    const float* __restrict__ p1 = img1 + (size_t)plane * (IMG_H * IMG_W);
    const float* __restrict__ p2 = img2 + (size_t)plane * (IMG_H * IMG_W);

    __shared__ __align__(16) float raw[11][2][RW];    // planar staging
    __shared__ __align__(16) u64   ileav[11][RW];     // (c,d) per col

    unsigned rbase;
    asm("{ .reg .u64 t; cvta.to.shared.u64 t, %1; cvt.u32.u64 %0, t; }"
        : "=r"(rbase) : "l"((const void*)raw));

    // loader: thread tx<72 owns one 16B chunk column (plane, pos) -- coalesced
    const int  larr  = (tx >= NCP) ? 1 : 0;
    const int  lpos  = tx - NCP * larr;
    const int  lgcol = col0 - 8 + lpos * 4;
    const bool lcolok = (tx < 2 * NCP) && ((unsigned)lgcol < (unsigned)IMG_W);
    const float* __restrict__ lbase = larr ? p2 : p1;
    const unsigned ldst = rbase + (unsigned)((larr * RW + lpos * 4) * 4);

    const u64 W2_0 = pk2(GW0, GW0), W2_1 = pk2(GW1, GW1), W2_2 = pk2(GW2, GW2);
    const u64 W2_3 = pk2(GW3, GW3), W2_4 = pk2(GW4, GW4), W2_5 = pk2(GW5, GW5);
    const u64 WT[11] = {W2_5, W2_4, W2_3, W2_2, W2_1, W2_0,
                        W2_1, W2_2, W2_3, W2_4, W2_5};
    const u64 NEG1 = pk2(-1.f, -1.f);

    u64 ring01[11], ringq[11];
#pragma unroll
    for (int k = 0; k < 11; ++k) { ring01[k] = 0ull; ringq[k] = 0ull; }

    float acc = 0.f;
    const float C1  = 1e-4f;
    const float C2  = 9e-4f;
    const float C2E = 9e-4f + 1e-6f;

    auto load_chunk = [&](int t) {
        if (tx < 2 * NCP) {
            const int base = row0 - 5 + t * 11;
#pragma unroll
            for (int r = 0; r < 11; ++r) {
                const int y = base + r;
                const bool ok = lcolok && ((unsigned)y < (unsigned)IMG_H);
                const int goff = ok ? (y * IMG_W + lgcol) : 0;
                cp16(ldst + (unsigned)(r * RAW_ROW_B), lbase + goff,
                     ok ? 16u : 0u);
            }
        }
        asm volatile("cp.async.commit_group;");
    };

    load_chunk(0);

    // input rows n = t*11 + k; outputs for n in [10, nlim)
#pragma unroll 1
    for (int t = 0; t < tmax; ++t) {
        asm volatile("cp.async.wait_group 0;");
        __syncthreads();   // raw = chunk t; also: ileav consumed (t-1)

        // transform raw -> ileav (out of place, disjoint): quad g of row r
        {
#pragma unroll 1
            for (int j = tx; j < PRE_TASKS; j += 128) {
                const int r = j / NCP;
                const int g = j - r * NCP;
                const float4 A = *(const float4*)&raw[r][0][g * 4];  // a0..a3
                const float4 B = *(const float4*)&raw[r][1][g * 4];  // b0..b3
                float4 o0, o1;
                o0.x = A.x + B.x;  o0.y = A.x - B.x;   // c0 d0
                o0.z = A.y + B.y;  o0.w = A.y - B.y;   // c1 d1
                o1.x = A.z + B.z;  o1.y = A.z - B.z;   // c2 d2
                o1.z = A.w + B.w;  o1.w = A.w - B.w;   // c3 d3
                float4* dst = (float4*)&ileav[r][g * 4];
                dst[0] = o0;
                dst[1] = o1;
            }
        }
        __syncthreads();   // ileav ready; raw free

        if (t < tmax - 1) load_chunk(t + 1);   // overlaps consume below

#pragma unroll
        for (int k = 0; k < 11; ++k) {
            const u64* srow = ileav[k];
            u64 h01 = 0ull, hq = 0ull;
#pragma unroll
            for (int i = 0; i < 11; ++i) {
                const u64 vv = srow[tx + 3 + i];   // LDS.64 (c,d)
                const u64 w  = WT[i];
                h01 = fma2(w, vv, h01);            // (+wc, +wd)
                const u64 p = mul2(w, vv);         // (wc, wd)
                hq  = fma2(p, vv, hq);             // (+wc^2, +wd^2)
            }
            ring01[k] = h01;
            ringq [k] = hq;

            const int n = t * 11 + k;
            if (n >= 10 && n < nlim) {
                u64 m12 = 0ull, qv = 0ull;
#pragma unroll
                for (int j = 0; j < 11; ++j) {
                    const int s = (k + 1 + j) % 11;   // static after unroll
                    const u64 w = WT[j];
                    m12 = fma2(w, ring01[s], m12);    // (C, D)
                    qv  = fma2(w, ringq [s], qv);     // (Qc, Qd)
                }
                const u64 cd2 = mul2(m12, m12);           // (C^2, D^2)
                const u64 ev  = fma2(cd2, NEG1, qv);      // (Ec, Ed)
                const float2 s2 = upk2(cd2);
                const float2 e2 = upk2(ev);
                const float M = s2.x - s2.y;   // 4*mu1*mu2
                const float P = s2.x + s2.y;   // 2*(mu1^2+mu2^2)
                const float S = e2.x - e2.y;   // 4*sig12
                const float T = e2.x + e2.y;   // 2*sigpp
                const float num = fmaf(0.5f, M, C1) * fmaf(0.5f, S, C2);
                const float den = fmaf(0.5f, P, C1) * fmaf(0.5f, T, C2E);
                acc += __fdividef(num, den);
            }
        }
        // next iteration's top sync doubles as the "ileav consumed" barrier.
    }

#pragma unroll
    for (int o = 16; o > 0; o >>= 1)
        acc += __shfl_xor_sync(0xFFFFFFFFu, acc, o);

    __shared__ float wsum[4];
    if ((tx & 31) == 0) wsum[tx >> 5] = acc;
    __syncthreads();

    if (tx == 0) {
        const float s = wsum[0] + wsum[1] + wsum[2] + wsum[3];
        atomicAdd(&g_acc, (double)s);
        __threadfence();
        const unsigned int done = atomicAdd(&g_count, 1u);
        if (done == (unsigned)(N_BLOCKS - 1)) {
            const double total = atomicAdd(&g_acc, 0.0);
            out[0] = (float)(total / TOTAL_PIX);
            g_acc = 0.0;
            g_count = 0u;
            __threadfence();
        }
    }
}

extern "C" void kernel_launch(void* const* d_in, const int* in_sizes, int n_in,
                              void* d_out, int out_size) {
    const float* img1 = (const float*)d_in[0];
    const float* img2 = (const float*)d_in[1];
    float* out = (float*)d_out;
    (void)in_sizes; (void)n_in; (void)out_size;

    dim3 grid(N_PLANES, 4, N_BANDS);
    ssim_kernel<<<grid, 128>>>(img1, img2, out);
}

// round 16
// speedup vs baseline: 1.3511x; 1.0856x over previous
#include <cuda_runtime.h>

// ---------------------------------------------------------------------------
// SSIM (16,3,512,512) fp32, 11x11 gaussian (sigma=1.5), zero padding.
// Round-16 (base R15, 76.3us): gaussian-symmetry pairing in the horizontal
// pass. w[i]==w[10-i], so:
//   linear:    add2(v_i, v_{10-i}) + fma2            (2 ops / 2 taps)
//   quadratic: mul2 + fma2 (v_i^2+v_r^2) + fma2      (3 ops / 2 taps)
//   center:    p = mul2(w0,v5) seeds h01; hq = mul2(p,v5)   (2 ops)
// 27 fma2/row (was 33) -- ~10% off total fma-pipe work, LDS unchanged.
// All else identical to R15 (LPT bands, cp16 loader, out-of-place (c,d)
// transform, interleaved consumer, packed vertical, epilogue).
// ---------------------------------------------------------------------------

#define IMG_H 512
#define IMG_W 512
#define N_PLANES 48
#define N_BANDS 10
#define N_BLOCKS (48 * 4 * N_BANDS)
#define TOTAL_PIX 12582912.0

#define GW0 0.26601172f
#define GW1 0.21300554f
#define GW2 0.10936069f
#define GW3 0.03600077f
#define GW4 0.00759876f
#define GW5 0.00102842f

__device__ double g_acc;
__device__ unsigned int g_count;

typedef unsigned long long u64;

__device__ __forceinline__ u64 pk2(float lo, float hi) {
    u64 r; asm("mov.b64 %0, {%1, %2};" : "=l"(r) : "f"(lo), "f"(hi)); return r;
}
__device__ __forceinline__ float2 upk2(u64 v) {
    float2 r; asm("mov.b64 {%0, %1}, %2;" : "=f"(r.x), "=f"(r.y) : "l"(v)); return r;
}
__device__ __forceinline__ u64 fma2(u64 a, u64 b, u64 c) {
    u64 d; asm("fma.rn.f32x2 %0, %1, %2, %3;" : "=l"(d) : "l"(a), "l"(b), "l"(c)); return d;
}
__device__ __forceinline__ u64 mul2(u64 a, u64 b) {
    u64 d; asm("mul.rn.f32x2 %0, %1, %2;" : "=l"(d) : "l"(a), "l"(b)); return d;
}
__device__ __forceinline__ u64 add2(u64 a, u64 b) {
    u64 d; asm("add.rn.f32x2 %0, %1, %2;" : "=l"(d) : "l"(a), "l"(b)); return d;
}
__device__ __forceinline__ void cp16(unsigned dst, const float* src, unsigned rs) {
    asm volatile("cp.async.cg.shared.global [%0], [%1], 16, %2;"
                 :: "r"(dst), "l"(src), "r"(rs));
}

// local cols 0..143  <->  global cols col0-8 .. col0+135
// consumer taps for thread tx: slots tx+3 .. tx+13 (max 140 < 144)
#define RW 144
#define NCP 36                            // 16B chunks per row per plane
#define RAW_ROW_B   (2 * RW * 4)          // 1152 B: plane a | plane b
#define PRE_TASKS   (11 * NCP)            // 396

__global__ __launch_bounds__(128, 7)
void ssim_kernel(const float* __restrict__ img1, const float* __restrict__ img2,
                 float* __restrict__ out) {
    // LPT band table: big bands first (low z), small drain-fillers last.
    const int BSTART[N_BANDS] = {0, 65, 130, 195, 260, 325, 390, 425, 460, 486};
    const int BSIZE [N_BANDS] = {65, 65, 65, 65, 65, 65, 35, 35, 26, 26};

    const int plane = blockIdx.x;     // 0..47
    const int strip = blockIdx.y;     // 0..3
    const int band  = blockIdx.z;     // 0..9
    const int tx    = threadIdx.x;

    const int col0 = strip * 128;
    const int row0 = BSTART[band];
    const int bsz  = BSIZE[band];
    const int nlim = 10 + bsz;
    const int tmax = (bsz + 20) / 11;     // ceil((bsz+10)/11)

    const float* __restrict__ p1 = img1 + (size_t)plane * (IMG_H * IMG_W);
    const float* __restrict__ p2 = img2 + (size_t)plane * (IMG_H * IMG_W);

    __shared__ __align__(16) float raw[11][2][RW];    // planar staging
    __shared__ __align__(16) u64   ileav[11][RW];     // (c,d) per col

    unsigned rbase;
    asm("{ .reg .u64 t; cvta.to.shared.u64 t, %1; cvt.u32.u64 %0, t; }"
        : "=r"(rbase) : "l"((const void*)raw));

    // loader: thread tx<72 owns one 16B chunk column (plane, pos) -- coalesced
    const int  larr  = (tx >= NCP) ? 1 : 0;
    const int  lpos  = tx - NCP * larr;
    const int  lgcol = col0 - 8 + lpos * 4;
    const bool lcolok = (tx < 2 * NCP) && ((unsigned)lgcol < (unsigned)IMG_W);
    const float* __restrict__ lbase = larr ? p2 : p1;
    const unsigned ldst = rbase + (unsigned)((larr * RW + lpos * 4) * 4);

    const u64 W2_0 = pk2(GW0, GW0), W2_1 = pk2(GW1, GW1), W2_2 = pk2(GW2, GW2);
    const u64 W2_3 = pk2(GW3, GW3), W2_4 = pk2(GW4, GW4), W2_5 = pk2(GW5, GW5);
    const u64 WT[11] = {W2_5, W2_4, W2_3, W2_2, W2_1, W2_0,
                        W2_1, W2_2, W2_3, W2_4, W2_5};
    // horizontal pair weights: pair j = taps (j, 10-j), j=0..4; center w0
    const u64 WP[5] = {W2_5, W2_4, W2_3, W2_2, W2_1};
    const u64 NEG1 = pk2(-1.f, -1.f);

    u64 ring01[11], ringq[11];
#pragma unroll
    for (int k = 0; k < 11; ++k) { ring01[k] = 0ull; ringq[k] = 0ull; }

    float acc = 0.f;
    const float C1  = 1e-4f;
    const float C2  = 9e-4f;
    const float C2E = 9e-4f + 1e-6f;

    auto load_chunk = [&](int t) {
        if (tx < 2 * NCP) {
            const int base = row0 - 5 + t * 11;
#pragma unroll
            for (int r = 0; r < 11; ++r) {
                const int y = base + r;
                const bool ok = lcolok && ((unsigned)y < (unsigned)IMG_H);
                const int goff = ok ? (y * IMG_W + lgcol) : 0;
                cp16(ldst + (unsigned)(r * RAW_ROW_B), lbase + goff,
                     ok ? 16u : 0u);
            }
        }
        asm volatile("cp.async.commit_group;");
    };

    load_chunk(0);

    // input rows n = t*11 + k; outputs for n in [10, nlim)
#pragma unroll 1
    for (int t = 0; t < tmax; ++t) {
        asm volatile("cp.async.wait_group 0;");
        __syncthreads();   // raw = chunk t; also: ileav consumed (t-1)

        // transform raw -> ileav (out of place, disjoint): quad g of row r
        {
#pragma unroll 1
            for (int j = tx; j < PRE_TASKS; j += 128) {
                const int r = j / NCP;
                const int g = j - r * NCP;
                const float4 A = *(const float4*)&raw[r][0][g * 4];  // a0..a3
                const float4 B = *(const float4*)&raw[r][1][g * 4];  // b0..b3
                float4 o0, o1;
                o0.x = A.x + B.x;  o0.y = A.x - B.x;   // c0 d0
                o0.z = A.y + B.y;  o0.w = A.y - B.y;   // c1 d1
                o1.x = A.z + B.z;  o1.y = A.z - B.z;   // c2 d2
                o1.z = A.w + B.w;  o1.w = A.w - B.w;   // c3 d3
                float4* dst = (float4*)&ileav[r][g * 4];
                dst[0] = o0;
                dst[1] = o1;
            }
        }
        __syncthreads();   // ileav ready; raw free

        if (t < tmax - 1) load_chunk(t + 1);   // overlaps consume below

#pragma unroll
        for (int k = 0; k < 11; ++k) {
            const u64* srow = ileav[k];
            u64 v[11];
#pragma unroll
            for (int i = 0; i < 11; ++i) v[i] = srow[tx + 3 + i];  // LDS.64

            // center tap (w0): p seeds h01, p*v5 seeds hq
            u64 h01 = mul2(W2_0, v[5]);
            u64 hq  = mul2(h01, v[5]);
            // symmetric pairs (j, 10-j), j=0..4
#pragma unroll
            for (int j = 0; j < 5; ++j) {
                const u64 w  = WP[j];
                const u64 s  = add2(v[j], v[10 - j]);            // v_l + v_r
                h01 = fma2(w, s, h01);
                const u64 q = fma2(v[j], v[j], mul2(v[10 - j], v[10 - j]));
                hq  = fma2(w, q, hq);                            // + w*(vl^2+vr^2)
            }
            ring01[k] = h01;
            ringq [k] = hq;

            const int n = t * 11 + k;
            if (n >= 10 && n < nlim) {
                u64 m12 = 0ull, qv = 0ull;
#pragma unroll
                for (int j = 0; j < 11; ++j) {
                    const int s = (k + 1 + j) % 11;   // static after unroll
                    const u64 w = WT[j];
                    m12 = fma2(w, ring01[s], m12);    // (C, D)
                    qv  = fma2(w, ringq [s], qv);     // (Qc, Qd)
                }
                const u64 cd2 = mul2(m12, m12);           // (C^2, D^2)
                const u64 ev  = fma2(cd2, NEG1, qv);      // (Ec, Ed)
                const float2 s2 = upk2(cd2);
                const float2 e2 = upk2(ev);
                const float M = s2.x - s2.y;   // 4*mu1*mu2
                const float P = s2.x + s2.y;   // 2*(mu1^2+mu2^2)
                const float S = e2.x - e2.y;   // 4*sig12
                const float T = e2.x + e2.y;   // 2*sigpp
                const float num = fmaf(0.5f, M, C1) * fmaf(0.5f, S, C2);
                const float den = fmaf(0.5f, P, C1) * fmaf(0.5f, T, C2E);
                acc += __fdividef(num, den);
            }
        }
        // next iteration's top sync doubles as the "ileav consumed" barrier.
    }

#pragma unroll
    for (int o = 16; o > 0; o >>= 1)
        acc += __shfl_xor_sync(0xFFFFFFFFu, acc, o);

    __shared__ float wsum[4];
    if ((tx & 31) == 0) wsum[tx >> 5] = acc;
    __syncthreads();

    if (tx == 0) {
        const float s = wsum[0] + wsum[1] + wsum[2] + wsum[3];
        atomicAdd(&g_acc, (double)s);
        __threadfence();
        const unsigned int done = atomicAdd(&g_count, 1u);
        if (done == (unsigned)(N_BLOCKS - 1)) {
            const double total = atomicAdd(&g_acc, 0.0);
            out[0] = (float)(total / TOTAL_PIX);
            g_acc = 0.0;
            g_count = 0u;
            __threadfence();
        }
    }
}

extern "C" void kernel_launch(void* const* d_in, const int* in_sizes, int n_in,
                              void* d_out, int out_size) {
    const float* img1 = (const float*)d_in[0];
    const float* img2 = (const float*)d_in[1];
    float* out = (float*)d_out;
    (void)in_sizes; (void)n_in; (void)out_size;

    dim3 grid(N_PLANES, 4, N_BANDS);
    ssim_kernel<<<grid, 128>>>(img1, img2, out);
}